// round 9
// baseline (speedup 1.0000x reference)
#include <cuda_runtime.h>
#include <cuda_bf16.h>
#include <cstdint>

// out[t, :] = weight[words[t], :] * mask[words[t]]
// words: (16384,) int32, weight: (50257, 768) f32, mask: (50257,) f32
//
// L2-residency theory: the ~14K distinct gathered weight rows (~41MB) are
// identical across graph replays and fit in L2 (126MB) with the output
// (48MB). Pin weight reads as evict_last via createpolicy + cache_hint
// (sm_103a ptxas rejects the direct .L2::evict_last qualifier on v4 loads).
// Structure: 8 tokens/CTA, front-batched independent LDG.128 (MLP~8),
// thread i owns float4 column i of each row (fully coalesced).

static constexpr int DIM = 768;
static constexpr int VEC = 4;                 // float4
static constexpr int THREADS = DIM / VEC;     // 192
static constexpr int TOK_PER_CTA = 8;

__device__ __forceinline__ uint64_t make_evict_last_policy()
{
    uint64_t pol;
    asm("createpolicy.fractional.L2::evict_last.b64 %0, 1.0;" : "=l"(pol));
    return pol;
}

__device__ __forceinline__ float4 ldg_nc_el(const float4* p, uint64_t pol)
{
    float4 v;
    asm volatile("ld.global.nc.L2::cache_hint.v4.f32 {%0,%1,%2,%3}, [%4], %5;"
                 : "=f"(v.x), "=f"(v.y), "=f"(v.z), "=f"(v.w)
                 : "l"(p), "l"(pol));
    return v;
}

__device__ __forceinline__ float ldg_nc_el_f(const float* p, uint64_t pol)
{
    float v;
    asm volatile("ld.global.nc.L2::cache_hint.f32 %0, [%1], %2;"
                 : "=f"(v) : "l"(p), "l"(pol));
    return v;
}

__global__ __launch_bounds__(THREADS)
void embedding_dropout_k8(const int* __restrict__ words,
                          const float* __restrict__ weight,
                          const float* __restrict__ mask,
                          float* __restrict__ out)
{
    const uint64_t pol = make_evict_last_policy();
    const int t0 = blockIdx.x * TOK_PER_CTA;

    // 8 token ids via two int4 loads (uniform addr -> L1 broadcast).
    const int4* wi = reinterpret_cast<const int4*>(words + t0);
    const int4 i0 = __ldg(&wi[0]);
    const int4 i1 = __ldg(&wi[1]);
    const int rows[TOK_PER_CTA] = { i0.x, i0.y, i0.z, i0.w,
                                    i1.x, i1.y, i1.z, i1.w };

    // Front-batch mask loads (small table, keep resident too).
    float m[TOK_PER_CTA];
#pragma unroll
    for (int k = 0; k < TOK_PER_CTA; ++k)
        m[k] = ldg_nc_el_f(&mask[rows[k]], pol);

    // Front-batch 8 independent row gathers, pinned high-priority in L2.
    float4 v[TOK_PER_CTA];
#pragma unroll
    for (int k = 0; k < TOK_PER_CTA; ++k) {
        const float4* src =
            reinterpret_cast<const float4*>(weight + (size_t)rows[k] * DIM);
        v[k] = ldg_nc_el(&src[threadIdx.x], pol);
    }

    // Scale + store (default policy: writeback, don't compete with weight).
#pragma unroll
    for (int k = 0; k < TOK_PER_CTA; ++k) {
        v[k].x *= m[k]; v[k].y *= m[k]; v[k].z *= m[k]; v[k].w *= m[k];
        float4* dst = reinterpret_cast<float4*>(out + (size_t)(t0 + k) * DIM);
        dst[threadIdx.x] = v[k];
    }
}

// Tail kernel: one token per CTA (only used if n_tokens % 8 != 0).
__global__ __launch_bounds__(THREADS)
void embedding_dropout_k1(const int* __restrict__ words,
                          const float* __restrict__ weight,
                          const float* __restrict__ mask,
                          float* __restrict__ out,
                          int t_base, int n_tokens)
{
    const uint64_t pol = make_evict_last_policy();
    const int t = t_base + blockIdx.x;
    if (t >= n_tokens) return;
    const int row = __ldg(&words[t]);
    const float m = ldg_nc_el_f(&mask[row], pol);
    const float4* src = reinterpret_cast<const float4*>(weight + (size_t)row * DIM);
    float4 v = ldg_nc_el(&src[threadIdx.x], pol);
    v.x *= m; v.y *= m; v.z *= m; v.w *= m;
    reinterpret_cast<float4*>(out + (size_t)t * DIM)[threadIdx.x] = v;
}

extern "C" void kernel_launch(void* const* d_in, const int* in_sizes, int n_in,
                              void* d_out, int out_size)
{
    const int*   words  = (const int*)d_in[0];
    const float* weight = (const float*)d_in[1];
    const float* mask   = (const float*)d_in[2];
    float*       out    = (float*)d_out;

    const int n_tokens = in_sizes[0];            // 16384
    const int n_full   = n_tokens / TOK_PER_CTA; // 2048
    const int tail     = n_tokens - n_full * TOK_PER_CTA;

    if (n_full > 0)
        embedding_dropout_k8<<<n_full, THREADS>>>(words, weight, mask, out);
    if (tail > 0)
        embedding_dropout_k1<<<tail, THREADS>>>(words, weight, mask, out,
                                                n_full * TOK_PER_CTA, n_tokens);
}

// round 10
// speedup vs baseline: 1.0522x; 1.0522x over previous
#include <cuda_runtime.h>
#include <cuda_bf16.h>
#include <cstdint>

// out[t, :] = weight[words[t], :] * mask[words[t]]
// words: (16384,) int32, weight: (50257, 768) f32, mask: (50257,) f32
//
// R5 theory: previous kernel compiled to regs=32 -> ptxas serialized the
// "front-batched" 8 gathers (effective MLP~2) -> latency-bound at 40% DRAM.
// Fix: __launch_bounds__(192, 4) gives ~84 regs/thread so all 8 LDG.128
// can genuinely be in flight. 8 named float4 destinations, loads first,
// multiply+store after. Thread i owns float4 column i (fully coalesced).

static constexpr int DIM = 768;
static constexpr int VEC = 4;                 // float4
static constexpr int THREADS = DIM / VEC;     // 192
static constexpr int TOK_PER_CTA = 8;

__global__ __launch_bounds__(THREADS, 4)
void embedding_dropout_k8(const int* __restrict__ words,
                          const float* __restrict__ weight,
                          const float* __restrict__ mask,
                          float* __restrict__ out)
{
    const int t0 = blockIdx.x * TOK_PER_CTA;
    const int c  = threadIdx.x;

    // 8 token ids via two int4 loads (uniform addr -> L1 broadcast).
    const int4* wi = reinterpret_cast<const int4*>(words + t0);
    const int4 i0 = __ldg(&wi[0]);
    const int4 i1 = __ldg(&wi[1]);

    const size_t r0 = (size_t)i0.x * DIM, r1 = (size_t)i0.y * DIM;
    const size_t r2 = (size_t)i0.z * DIM, r3 = (size_t)i0.w * DIM;
    const size_t r4 = (size_t)i1.x * DIM, r5 = (size_t)i1.y * DIM;
    const size_t r6 = (size_t)i1.z * DIM, r7 = (size_t)i1.w * DIM;

    // Independent mask loads (issue early, consumed late).
    const float m0 = __ldg(&mask[i0.x]), m1 = __ldg(&mask[i0.y]);
    const float m2 = __ldg(&mask[i0.z]), m3 = __ldg(&mask[i0.w]);
    const float m4 = __ldg(&mask[i1.x]), m5 = __ldg(&mask[i1.y]);
    const float m6 = __ldg(&mask[i1.z]), m7 = __ldg(&mask[i1.w]);

    // 8 genuinely independent LDG.128 gathers -> MLP = 8 in SASS.
    const float4 v0 = __ldg(reinterpret_cast<const float4*>(weight + r0) + c);
    const float4 v1 = __ldg(reinterpret_cast<const float4*>(weight + r1) + c);
    const float4 v2 = __ldg(reinterpret_cast<const float4*>(weight + r2) + c);
    const float4 v3 = __ldg(reinterpret_cast<const float4*>(weight + r3) + c);
    const float4 v4 = __ldg(reinterpret_cast<const float4*>(weight + r4) + c);
    const float4 v5 = __ldg(reinterpret_cast<const float4*>(weight + r5) + c);
    const float4 v6 = __ldg(reinterpret_cast<const float4*>(weight + r6) + c);
    const float4 v7 = __ldg(reinterpret_cast<const float4*>(weight + r7) + c);

    float4* dst = reinterpret_cast<float4*>(out + (size_t)t0 * DIM) + c;
    const int stride = DIM / VEC;  // float4s per token row

    float4 w;
    w = v0; w.x *= m0; w.y *= m0; w.z *= m0; w.w *= m0; dst[0 * stride] = w;
    w = v1; w.x *= m1; w.y *= m1; w.z *= m1; w.w *= m1; dst[1 * stride] = w;
    w = v2; w.x *= m2; w.y *= m2; w.z *= m2; w.w *= m2; dst[2 * stride] = w;
    w = v3; w.x *= m3; w.y *= m3; w.z *= m3; w.w *= m3; dst[3 * stride] = w;
    w = v4; w.x *= m4; w.y *= m4; w.z *= m4; w.w *= m4; dst[4 * stride] = w;
    w = v5; w.x *= m5; w.y *= m5; w.z *= m5; w.w *= m5; dst[5 * stride] = w;
    w = v6; w.x *= m6; w.y *= m6; w.z *= m6; w.w *= m6; dst[6 * stride] = w;
    w = v7; w.x *= m7; w.y *= m7; w.z *= m7; w.w *= m7; dst[7 * stride] = w;
}

// Tail kernel: one token per CTA (only used if n_tokens % 8 != 0).
__global__ __launch_bounds__(THREADS)
void embedding_dropout_k1(const int* __restrict__ words,
                          const float* __restrict__ weight,
                          const float* __restrict__ mask,
                          float* __restrict__ out,
                          int t_base, int n_tokens)
{
    const int t = t_base + blockIdx.x;
    if (t >= n_tokens) return;
    const int row = __ldg(&words[t]);
    const float m = __ldg(&mask[row]);
    const float4* src = reinterpret_cast<const float4*>(weight + (size_t)row * DIM);
    float4 v = __ldg(&src[threadIdx.x]);
    v.x *= m; v.y *= m; v.z *= m; v.w *= m;
    reinterpret_cast<float4*>(out + (size_t)t * DIM)[threadIdx.x] = v;
}

extern "C" void kernel_launch(void* const* d_in, const int* in_sizes, int n_in,
                              void* d_out, int out_size)
{
    const int*   words  = (const int*)d_in[0];
    const float* weight = (const float*)d_in[1];
    const float* mask   = (const float*)d_in[2];
    float*       out    = (float*)d_out;

    const int n_tokens = in_sizes[0];            // 16384
    const int n_full   = n_tokens / TOK_PER_CTA; // 2048
    const int tail     = n_tokens - n_full * TOK_PER_CTA;

    if (n_full > 0)
        embedding_dropout_k8<<<n_full, THREADS>>>(words, weight, mask, out);
    if (tail > 0)
        embedding_dropout_k1<<<tail, THREADS>>>(words, weight, mask, out,
                                                n_full * TOK_PER_CTA, n_tokens);
}